// round 15
// baseline (speedup 1.0000x reference)
#include <cuda_runtime.h>
#include <cuda_bf16.h>
#include <cstdint>
#include <cstddef>

#define L_SEQ 4096
#define SDIM  384
#define DST   16
#define BATCH 4
#define M_TOT (BATCH * L_SEQ)      // 16384
#define P_TOT (2 * SDIM + 2 * DST) // 800
#define NP_PAD 896                 // 7*128 padded proj output dim
#define NCH   (BATCH * SDIM)
#define T_CHK 32
#define N_CHK (L_SEQ / T_CHK)      // 128
#define CSTATES (NCH * DST)        // 24576

// ---------------- scratch (referenced ONLY inside device code) ----------------
__device__ __align__(16) float g_xin[M_TOT * SDIM];
__device__ __align__(16) float g_dsp[M_TOT * SDIM];
__device__ __align__(16) float g_Bm [M_TOT * DST];
__device__ __align__(16) float g_Cm [M_TOT * DST];
__device__ __align__(16) float g_aP [N_CHK * CSTATES];
__device__ __align__(16) float g_hP [N_CHK * CSTATES];
__device__ __align__(16) float g_h0 [N_CHK * CSTATES];

__device__ __align__(16) __nv_bfloat16 g_xt_hi[(size_t)M_TOT * SDIM];
__device__ __align__(16) __nv_bfloat16 g_xt_lo[(size_t)M_TOT * SDIM];
__device__ __align__(16) __nv_bfloat16 g_yhi [(size_t)M_TOT * SDIM];
__device__ __align__(16) __nv_bfloat16 g_ylo [(size_t)M_TOT * SDIM];
__device__ __align__(16) __nv_bfloat16 g_Wp_hi[NP_PAD * SDIM];
__device__ __align__(16) __nv_bfloat16 g_Wp_lo[NP_PAD * SDIM];
__device__ __align__(16) __nv_bfloat16 g_Wo_hi[SDIM * SDIM];
__device__ __align__(16) __nv_bfloat16 g_Wo_lo[SDIM * SDIM];

__device__ __forceinline__ float softplusf(float z) {
    if (z > 20.f) return z;
    return log1pf(__expf(z));
}

__device__ __forceinline__ uint32_t smem_u32(const void* p) {
    uint32_t a;
    asm("{ .reg .u64 t; cvta.to.shared.u64 t, %1; cvt.u32.u64 %0, t; }" : "=r"(a) : "l"(p));
    return a;
}

__device__ __forceinline__ void cp16(uint32_t saddr, const void* gptr) {
    asm volatile("cp.async.cg.shared.global [%0], [%1], 16;" :: "r"(saddr), "l"(gptr));
}
__device__ __forceinline__ void cp_commit() {
    asm volatile("cp.async.commit_group;" ::: "memory");
}
template<int N>
__device__ __forceinline__ void cp_wait() {
    asm volatile("cp.async.wait_group %0;" :: "n"(N) : "memory");
}

__device__ __forceinline__ void ldm_x4(uint32_t* r, uint32_t addr) {
    asm volatile("ldmatrix.sync.aligned.m8n8.x4.shared.b16 {%0,%1,%2,%3}, [%4];"
                 : "=r"(r[0]), "=r"(r[1]), "=r"(r[2]), "=r"(r[3]) : "r"(addr));
}
__device__ __forceinline__ void mma16816(float* c, const uint32_t* a, const uint32_t* b) {
    asm volatile(
        "mma.sync.aligned.m16n8k16.row.col.f32.bf16.bf16.f32 "
        "{%0,%1,%2,%3}, {%4,%5,%6,%7}, {%8,%9}, {%0,%1,%2,%3};"
        : "+f"(c[0]), "+f"(c[1]), "+f"(c[2]), "+f"(c[3])
        : "r"(a[0]), "r"(a[1]), "r"(a[2]), "r"(a[3]), "r"(b[0]), "r"(b[1]));
}

// ============================ prep kernels ============================
__global__ __launch_bounds__(256) void transpose_split_kernel(const float* __restrict__ x)
{
    __shared__ float T[32][33];
    const int tx = threadIdx.x, ty = threadIdx.y;
    const int l0 = blockIdx.x * 32, c0 = blockIdx.y * 32, b = blockIdx.z;
#pragma unroll
    for (int i = 0; i < 4; ++i) {
        int c = c0 + ty + i * 8;
        T[ty + i * 8][tx] = x[((size_t)b * SDIM + c) * L_SEQ + l0 + tx];
    }
    __syncthreads();
#pragma unroll
    for (int i = 0; i < 4; ++i) {
        int l = l0 + ty + i * 8;
        size_t m = (size_t)b * L_SEQ + l;
        float v = T[tx][ty + i * 8];
        __nv_bfloat16 hi = __float2bfloat16(v);
        float lo = v - __bfloat162float(hi);
        g_xt_hi[m * SDIM + c0 + tx] = hi;
        g_xt_lo[m * SDIM + c0 + tx] = __float2bfloat16(lo);
    }
}

__global__ __launch_bounds__(256) void convWp_kernel(const float* __restrict__ W)
{
    int idx = blockIdx.x * 256 + threadIdx.x;
    if (idx >= NP_PAD * SDIM) return;
    int n = idx / SDIM;
    float v = (n < P_TOT) ? W[idx] : 0.f;
    __nv_bfloat16 h = __float2bfloat16(v);
    g_Wp_hi[idx] = h;
    g_Wp_lo[idx] = __float2bfloat16(v - __bfloat162float(h));
}

__global__ __launch_bounds__(256) void convWo_kernel(const float* __restrict__ W)
{
    int idx = blockIdx.x * 256 + threadIdx.x;
    if (idx >= SDIM * SDIM) return;
    float v = W[idx];
    __nv_bfloat16 h = __float2bfloat16(v);
    g_Wo_hi[idx] = h;
    g_Wo_lo[idx] = __float2bfloat16(v - __bfloat162float(h));
}

// ============================ HMMA GEMM (term-major MMA ordering) ============================
// D[128m x 128n] = (Ahi+Alo)[m][384] . (Bhi+Blo)[n][384]^T  (3-term split)
// 512 threads = 16 warps as 4(m) x 4(n); warp tile 32x32; BK=32; 2-stage cp.async,
// wait<1>. MMA issued term-major: consecutive HMMAs hit DIFFERENT accumulators.
#define TSTR 40                         // smem stride (bf16 elements); row = 80B
#define TILE_E (128 * TSTR)             // bf16 elements per tile
#define STAGE_E (4 * TILE_E)            // 4 tiles per stage
#define GEMM_SMEM (2 * STAGE_E * 2)     // 81920 bytes

template<int MODE>
__global__ __launch_bounds__(512, 2) void gemm_mma(
    const float* __restrict__ bias, const float* __restrict__ dtb,
    float* __restrict__ outp)
{
    extern __shared__ __nv_bfloat16 sm[];

    const int tid  = threadIdx.x;
    const int wid  = tid >> 5;
    const int lane = tid & 31;
    const int gid  = lane >> 2;      // 0..7
    const int tig  = lane & 3;       // 0..3
    const int n0 = blockIdx.x * 128;
    const int m0 = blockIdx.y * 128;
    const int wm = (wid >> 2) * 32;  // warp m offset {0,32,64,96}
    const int wn = (wid & 3) * 32;   // warp n offset {0,32,64,96}

    const __nv_bfloat16* gsrc[4];
    gsrc[0] = (MODE == 0 ? g_xt_hi : g_yhi) + (size_t)m0 * SDIM;
    gsrc[1] = (MODE == 0 ? g_xt_lo : g_ylo) + (size_t)m0 * SDIM;
    gsrc[2] = (MODE == 0 ? g_Wp_hi : g_Wo_hi) + (size_t)n0 * SDIM;
    gsrc[3] = (MODE == 0 ? g_Wp_lo : g_Wo_lo) + (size_t)n0 * SDIM;

    const uint32_t sbase = smem_u32(sm);
    const int row0 = tid >> 2, seg = tid & 3;   // one 16B chunk per (tile,thread)

    auto prefetch = [&](int stage, int k0g) {
        uint32_t sst = sbase + (uint32_t)stage * STAGE_E * 2;
#pragma unroll
        for (int t4 = 0; t4 < 4; ++t4) {
            uint32_t sa = sst + (uint32_t)(t4 * TILE_E + row0 * TSTR + seg * 8) * 2;
            cp16(sa, gsrc[t4] + (size_t)row0 * SDIM + k0g + seg * 8);
        }
        cp_commit();
    };

    float acc[2][4][4];
#pragma unroll
    for (int i = 0; i < 2; ++i)
#pragma unroll
        for (int j = 0; j < 4; ++j)
#pragma unroll
            for (int c = 0; c < 4; ++c) acc[i][j][c] = 0.f;

    prefetch(0, 0);
    prefetch(1, 32);

    // ldmatrix lane-address components
    const int a_row  = wm + (lane & 15);                       // + mt*16
    const int a_koff = (lane >> 4) * 8;                        // 0 or 8
    // merged B x4: mats {b0(nt=2p), b1(2p), b0(2p+1), b1(2p+1)}
    const int b_row4  = wn + (lane & 7) + ((lane >> 4) << 3);  // + p*16
    const int b_koff4 = ((lane >> 3) & 1) * 8;

    const int KC = SDIM / 32;  // 12
    for (int kc = 0; kc < KC; ++kc) {
        const int cur = kc & 1;
        if (kc + 2 <= KC) cp_wait<1>(); else cp_wait<0>();
        __syncthreads();

        const uint32_t stile = sbase + (uint32_t)(cur * STAGE_E) * 2;
        const uint32_t sAhi = stile;
        const uint32_t sAlo = stile + TILE_E * 2;
        const uint32_t sBhi = stile + 2 * TILE_E * 2;
        const uint32_t sBlo = stile + 3 * TILE_E * 2;

#pragma unroll
        for (int ks = 0; ks < 2; ++ks) {
            const int kk = ks * 16;
            uint32_t ah[2][4], al[2][4], bh[2][4], bl[2][4];
#pragma unroll
            for (int mt = 0; mt < 2; ++mt) {
                uint32_t off = (uint32_t)((a_row + mt * 16) * TSTR + kk + a_koff) * 2;
                ldm_x4(ah[mt], sAhi + off);
                ldm_x4(al[mt], sAlo + off);
            }
#pragma unroll
            for (int p = 0; p < 2; ++p) {
                uint32_t off = (uint32_t)((b_row4 + p * 16) * TSTR + kk + b_koff4) * 2;
                ldm_x4(bh[p], sBhi + off);
                ldm_x4(bl[p], sBlo + off);
            }
            // term-major: 8 independent HMMAs per term; each acc touched once per 8
#pragma unroll
            for (int mt = 0; mt < 2; ++mt)
#pragma unroll
                for (int nt = 0; nt < 4; ++nt)
                    mma16816(acc[mt][nt], ah[mt], &bh[nt >> 1][(nt & 1) * 2]);
#pragma unroll
            for (int mt = 0; mt < 2; ++mt)
#pragma unroll
                for (int nt = 0; nt < 4; ++nt)
                    mma16816(acc[mt][nt], ah[mt], &bl[nt >> 1][(nt & 1) * 2]);
#pragma unroll
            for (int mt = 0; mt < 2; ++mt)
#pragma unroll
                for (int nt = 0; nt < 4; ++nt)
                    mma16816(acc[mt][nt], al[mt], &bh[nt >> 1][(nt & 1) * 2]);
        }
        if (kc + 2 < KC) {
            __syncthreads();
            prefetch(cur, (kc + 2) * 32);
        }
    }

    // ---------------- epilogue ----------------
    // C frag: c0=D[gid][2t], c1=D[gid][2t+1], c2=D[gid+8][2t], c3=D[gid+8][2t+1]
    if (MODE == 0) {
#pragma unroll
        for (int mt = 0; mt < 2; ++mt) {
#pragma unroll
            for (int nt = 0; nt < 4; ++nt) {
                const int m = m0 + wm + mt * 16 + gid;
                const int n = n0 + wn + nt * 8 + tig * 2;
#pragma unroll
                for (int half = 0; half < 2; ++half) {
                    const int mm = m + half * 8;
                    const float v0 = acc[mt][nt][half * 2 + 0];
                    const float v1 = acc[mt][nt][half * 2 + 1];
                    if (n < SDIM) {
                        g_xin[(size_t)mm * SDIM + n]     = v0 + bias[n];
                        g_xin[(size_t)mm * SDIM + n + 1] = v1 + bias[n + 1];
                    } else if (n < 2 * SDIM) {
                        const int nd = n - SDIM;
                        g_dsp[(size_t)mm * SDIM + nd]     = softplusf(v0 + bias[n] + dtb[nd]);
                        g_dsp[(size_t)mm * SDIM + nd + 1] = softplusf(v1 + bias[n + 1] + dtb[nd + 1]);
                    } else if (n < 2 * SDIM + DST) {
                        const int nd = n - 2 * SDIM;
                        g_Bm[(size_t)mm * DST + nd]     = v0 + bias[n];
                        g_Bm[(size_t)mm * DST + nd + 1] = v1 + bias[n + 1];
                    } else if (n < P_TOT) {
                        const int nd = n - (2 * SDIM + DST);
                        g_Cm[(size_t)mm * DST + nd]     = v0 + bias[n];
                        g_Cm[(size_t)mm * DST + nd + 1] = v1 + bias[n + 1];
                    }
                }
            }
        }
    } else {
        // direct store: out[b][n][l] = D[m=l][n] + bias[n]
        const int bq = m0 >> 12;
        const int l0 = m0 & 4095;
#pragma unroll
        for (int mt = 0; mt < 2; ++mt) {
#pragma unroll
            for (int nt = 0; nt < 4; ++nt) {
                const int l = l0 + wm + mt * 16 + gid;
                const int n = n0 + wn + nt * 8 + tig * 2;
                const float b0 = bias[n], b1 = bias[n + 1];
                float* r0 = &outp[((size_t)(bq * SDIM + n)) * L_SEQ + l];
                float* r1 = &outp[((size_t)(bq * SDIM + n + 1)) * L_SEQ + l];
                r0[0] = acc[mt][nt][0] + b0;
                r1[0] = acc[mt][nt][1] + b1;
                r0[8] = acc[mt][nt][2] + b0;
                r1[8] = acc[mt][nt][3] + b1;
            }
        }
    }
}

// ============================ scan kernels ============================
__global__ __launch_bounds__(128) void scanA_kernel(const float* __restrict__ Alog)
{
    __shared__ float Bsh[T_CHK * DST];

    const int tid = threadIdx.x;
    const int d   = blockIdx.x * 128 + tid;
    const int b   = blockIdx.y;
    const int chk = blockIdx.z;
    const int t0  = chk * T_CHK;
    const int ch  = b * SDIM + d;

    {
        const float4* src = reinterpret_cast<const float4*>(&g_Bm[((size_t)(b * L_SEQ + t0)) * DST]);
        reinterpret_cast<float4*>(Bsh)[tid] = __ldg(&src[tid]);
    }

    float A[DST], h[DST], aP[DST];
#pragma unroll
    for (int n = 0; n < DST; ++n) {
        A[n] = -expf(__ldg(&Alog[d * DST + n]));
        h[n] = 0.f; aP[n] = 1.f;
    }
    __syncthreads();

    size_t ix = ((size_t)(b * L_SEQ + t0)) * SDIM + d;
#pragma unroll 4
    for (int t = 0; t < T_CHK; ++t) {
        float dt = __ldg(&g_dsp[ix]);
        float xv = __ldg(&g_xin[ix]);
        float u  = dt * xv;
        const float4* Bq = reinterpret_cast<const float4*>(&Bsh[t * DST]);
#pragma unroll
        for (int j = 0; j < 4; ++j) {
            float4 bv = Bq[j];
            float e0 = __expf(dt * A[j*4+0]);
            float e1 = __expf(dt * A[j*4+1]);
            float e2 = __expf(dt * A[j*4+2]);
            float e3 = __expf(dt * A[j*4+3]);
            h[j*4+0] = fmaf(e0, h[j*4+0], u * bv.x); aP[j*4+0] *= e0;
            h[j*4+1] = fmaf(e1, h[j*4+1], u * bv.y); aP[j*4+1] *= e1;
            h[j*4+2] = fmaf(e2, h[j*4+2], u * bv.z); aP[j*4+2] *= e2;
            h[j*4+3] = fmaf(e3, h[j*4+3], u * bv.w); aP[j*4+3] *= e3;
        }
        ix += SDIM;
    }

    const size_t ob = (size_t)chk * CSTATES + (size_t)ch * DST;
#pragma unroll
    for (int j = 0; j < 4; ++j) {
        *reinterpret_cast<float4*>(&g_aP[ob + j*4]) = make_float4(aP[j*4], aP[j*4+1], aP[j*4+2], aP[j*4+3]);
        *reinterpret_cast<float4*>(&g_hP[ob + j*4]) = make_float4(h [j*4], h [j*4+1], h [j*4+2], h [j*4+3]);
    }
}

__global__ __launch_bounds__(256) void scanB_kernel()
{
    const int tid = blockIdx.x * 256 + threadIdx.x;
    float h = 0.f;
#pragma unroll 8
    for (int c = 0; c < N_CHK; ++c) {
        g_h0[c * CSTATES + tid] = h;
        h = fmaf(__ldg(&g_aP[c * CSTATES + tid]), h, __ldg(&g_hP[c * CSTATES + tid]));
    }
}

__global__ __launch_bounds__(128) void scanC_kernel(
    const float* __restrict__ Alog, const float* __restrict__ Dp)
{
    __shared__ float Bsh[T_CHK * DST];
    __shared__ float Csh[T_CHK * DST];

    const int tid = threadIdx.x;
    const int d   = blockIdx.x * 128 + tid;
    const int b   = blockIdx.y;
    const int chk = blockIdx.z;
    const int t0  = chk * T_CHK;
    const int ch  = b * SDIM + d;

    {
        const float4* srcB = reinterpret_cast<const float4*>(&g_Bm[((size_t)(b * L_SEQ + t0)) * DST]);
        const float4* srcC = reinterpret_cast<const float4*>(&g_Cm[((size_t)(b * L_SEQ + t0)) * DST]);
        reinterpret_cast<float4*>(Bsh)[tid] = __ldg(&srcB[tid]);
        reinterpret_cast<float4*>(Csh)[tid] = __ldg(&srcC[tid]);
    }

    float A[DST], h[DST];
#pragma unroll
    for (int n = 0; n < DST; ++n)
        A[n] = -expf(__ldg(&Alog[d * DST + n]));
    {
        const size_t hb = (size_t)chk * CSTATES + (size_t)ch * DST;
#pragma unroll
        for (int j = 0; j < 4; ++j) {
            float4 v = *reinterpret_cast<const float4*>(&g_h0[hb + j*4]);
            h[j*4+0] = v.x; h[j*4+1] = v.y; h[j*4+2] = v.z; h[j*4+3] = v.w;
        }
    }
    const float Dd = __ldg(&Dp[d]);
    __syncthreads();

    size_t ix = ((size_t)(b * L_SEQ + t0)) * SDIM + d;
#pragma unroll 4
    for (int t = 0; t < T_CHK; ++t) {
        float dt = __ldg(&g_dsp[ix]);
        float xv = __ldg(&g_xin[ix]);
        float u  = dt * xv;
        float p  = xv * Dd;
        const float4* Bq = reinterpret_cast<const float4*>(&Bsh[t * DST]);
        const float4* Cq = reinterpret_cast<const float4*>(&Csh[t * DST]);
#pragma unroll
        for (int j = 0; j < 4; ++j) {
            float4 bv = Bq[j];
            float4 cv = Cq[j];
            float e0 = __expf(dt * A[j*4+0]);
            float e1 = __expf(dt * A[j*4+1]);
            float e2 = __expf(dt * A[j*4+2]);
            float e3 = __expf(dt * A[j*4+3]);
            h[j*4+0] = fmaf(e0, h[j*4+0], u * bv.x);
            h[j*4+1] = fmaf(e1, h[j*4+1], u * bv.y);
            h[j*4+2] = fmaf(e2, h[j*4+2], u * bv.z);
            h[j*4+3] = fmaf(e3, h[j*4+3], u * bv.w);
            p = fmaf(h[j*4+0], cv.x, p);
            p = fmaf(h[j*4+1], cv.y, p);
            p = fmaf(h[j*4+2], cv.z, p);
            p = fmaf(h[j*4+3], cv.w, p);
        }
        __nv_bfloat16 hi = __float2bfloat16(p);
        g_yhi[ix] = hi;
        g_ylo[ix] = __float2bfloat16(p - __bfloat162float(hi));
        ix += SDIM;
    }
}

// ============================ launch ============================
extern "C" void kernel_launch(void* const* d_in, const int* in_sizes, int n_in,
                              void* d_out, int out_size)
{
    const float* x    = (const float*)d_in[0];
    const float* Wp   = (const float*)d_in[1];
    const float* bp   = (const float*)d_in[2];
    const float* Alog = (const float*)d_in[3];
    const float* D    = (const float*)d_in[4];
    const float* dtb  = (const float*)d_in[5];
    const float* Wo   = (const float*)d_in[6];
    const float* bo   = (const float*)d_in[7];
    float* out = (float*)d_out;

    static bool attr_done = false;
    if (!attr_done) {
        cudaFuncSetAttribute(gemm_mma<0>, cudaFuncAttributeMaxDynamicSharedMemorySize, GEMM_SMEM);
        cudaFuncSetAttribute(gemm_mma<1>, cudaFuncAttributeMaxDynamicSharedMemorySize, GEMM_SMEM);
        attr_done = true;
    }

    // prep: transpose x to [m][k] split-bf16; split weights into device globals
    transpose_split_kernel<<<dim3(L_SEQ / 32, SDIM / 32, BATCH), dim3(32, 8)>>>(x);
    convWp_kernel<<<(NP_PAD * SDIM + 255) / 256, 256>>>(Wp);
    convWo_kernel<<<(SDIM * SDIM + 255) / 256, 256>>>(Wo);

    // proj GEMM (HMMA, term-major MMA) with fused region split + softplus
    gemm_mma<0><<<dim3(NP_PAD / 128, M_TOT / 128), 512, GEMM_SMEM>>>(bp, dtb, nullptr);

    // selective scan (chunked)
    dim3 gs(SDIM / 128, BATCH, N_CHK);
    scanA_kernel<<<gs, 128>>>(Alog);
    scanB_kernel<<<CSTATES / 256, 256>>>();
    scanC_kernel<<<gs, 128>>>(Alog, D);

    // out GEMM (HMMA, term-major MMA) with direct fragment stores
    gemm_mma<1><<<dim3(SDIM / 128, M_TOT / 128), 512, GEMM_SMEM>>>(bo, nullptr, out);
}

// round 16
// speedup vs baseline: 1.0300x; 1.0300x over previous
#include <cuda_runtime.h>
#include <cuda_bf16.h>
#include <cstdint>
#include <cstddef>

#define L_SEQ 4096
#define SDIM  384
#define DST   16
#define BATCH 4
#define M_TOT (BATCH * L_SEQ)      // 16384
#define P_TOT (2 * SDIM + 2 * DST) // 800
#define NP_PAD 896                 // 7*128 padded proj output dim
#define NCH   (BATCH * SDIM)
#define T_CHK 32
#define N_CHK (L_SEQ / T_CHK)      // 128
#define CSTATES (NCH * DST)        // 24576

// ---------------- scratch (referenced ONLY inside device code) ----------------
__device__ __align__(16) float g_xin[M_TOT * SDIM];
__device__ __align__(16) float g_dsp[M_TOT * SDIM];
__device__ __align__(16) float g_Bm [M_TOT * DST];
__device__ __align__(16) float g_Cm [M_TOT * DST];
__device__ __align__(16) float g_aP [N_CHK * CSTATES];
__device__ __align__(16) float g_hP [N_CHK * CSTATES];
__device__ __align__(16) float g_h0 [N_CHK * CSTATES];

__device__ __align__(16) __nv_bfloat16 g_xt_hi[(size_t)M_TOT * SDIM];
__device__ __align__(16) __nv_bfloat16 g_xt_lo[(size_t)M_TOT * SDIM];
__device__ __align__(16) __nv_bfloat16 g_yhi [(size_t)M_TOT * SDIM];
__device__ __align__(16) __nv_bfloat16 g_ylo [(size_t)M_TOT * SDIM];
__device__ __align__(16) __nv_bfloat16 g_Wp_hi[NP_PAD * SDIM];
__device__ __align__(16) __nv_bfloat16 g_Wp_lo[NP_PAD * SDIM];
__device__ __align__(16) __nv_bfloat16 g_Wo_hi[SDIM * SDIM];
__device__ __align__(16) __nv_bfloat16 g_Wo_lo[SDIM * SDIM];

__device__ __forceinline__ float softplusf(float z) {
    if (z > 20.f) return z;
    return log1pf(__expf(z));
}

__device__ __forceinline__ uint32_t smem_u32(const void* p) {
    uint32_t a;
    asm("{ .reg .u64 t; cvta.to.shared.u64 t, %1; cvt.u32.u64 %0, t; }" : "=r"(a) : "l"(p));
    return a;
}

__device__ __forceinline__ void cp16(uint32_t saddr, const void* gptr) {
    asm volatile("cp.async.cg.shared.global [%0], [%1], 16;" :: "r"(saddr), "l"(gptr));
}
__device__ __forceinline__ void cp_commit() {
    asm volatile("cp.async.commit_group;" ::: "memory");
}
template<int N>
__device__ __forceinline__ void cp_wait() {
    asm volatile("cp.async.wait_group %0;" :: "n"(N) : "memory");
}

__device__ __forceinline__ void ldm_x4(uint32_t* r, uint32_t addr) {
    asm volatile("ldmatrix.sync.aligned.m8n8.x4.shared.b16 {%0,%1,%2,%3}, [%4];"
                 : "=r"(r[0]), "=r"(r[1]), "=r"(r[2]), "=r"(r[3]) : "r"(addr));
}
__device__ __forceinline__ void mma16816(float* c, const uint32_t* a, const uint32_t* b) {
    asm volatile(
        "mma.sync.aligned.m16n8k16.row.col.f32.bf16.bf16.f32 "
        "{%0,%1,%2,%3}, {%4,%5,%6,%7}, {%8,%9}, {%0,%1,%2,%3};"
        : "+f"(c[0]), "+f"(c[1]), "+f"(c[2]), "+f"(c[3])
        : "r"(a[0]), "r"(a[1]), "r"(a[2]), "r"(a[3]), "r"(b[0]), "r"(b[1]));
}

// ============================ prep kernels ============================
__global__ __launch_bounds__(256) void transpose_split_kernel(const float* __restrict__ x)
{
    __shared__ float T[32][33];
    const int tx = threadIdx.x, ty = threadIdx.y;
    const int l0 = blockIdx.x * 32, c0 = blockIdx.y * 32, b = blockIdx.z;
#pragma unroll
    for (int i = 0; i < 4; ++i) {
        int c = c0 + ty + i * 8;
        T[ty + i * 8][tx] = x[((size_t)b * SDIM + c) * L_SEQ + l0 + tx];
    }
    __syncthreads();
#pragma unroll
    for (int i = 0; i < 4; ++i) {
        int l = l0 + ty + i * 8;
        size_t m = (size_t)b * L_SEQ + l;
        float v = T[tx][ty + i * 8];
        __nv_bfloat16 hi = __float2bfloat16(v);
        float lo = v - __bfloat162float(hi);
        g_xt_hi[m * SDIM + c0 + tx] = hi;
        g_xt_lo[m * SDIM + c0 + tx] = __float2bfloat16(lo);
    }
}

__global__ __launch_bounds__(256) void convWp_kernel(const float* __restrict__ W)
{
    int idx = blockIdx.x * 256 + threadIdx.x;
    if (idx >= NP_PAD * SDIM) return;
    int n = idx / SDIM;
    float v = (n < P_TOT) ? W[idx] : 0.f;
    __nv_bfloat16 h = __float2bfloat16(v);
    g_Wp_hi[idx] = h;
    g_Wp_lo[idx] = __float2bfloat16(v - __bfloat162float(h));
}

__global__ __launch_bounds__(256) void convWo_kernel(const float* __restrict__ W)
{
    int idx = blockIdx.x * 256 + threadIdx.x;
    if (idx >= SDIM * SDIM) return;
    float v = W[idx];
    __nv_bfloat16 h = __float2bfloat16(v);
    g_Wo_hi[idx] = h;
    g_Wo_lo[idx] = __float2bfloat16(v - __bfloat162float(h));
}

// ============================ HMMA GEMM (R14 config — best known) ============================
#define TSTR 40                         // smem stride (bf16 elements); row = 80B
#define TILE_E (128 * TSTR)             // bf16 elements per tile
#define STAGE_E (4 * TILE_E)            // 4 tiles per stage
#define GEMM_SMEM (2 * STAGE_E * 2)     // 81920 bytes

template<int MODE>
__global__ __launch_bounds__(512, 2) void gemm_mma(
    const float* __restrict__ bias, const float* __restrict__ dtb,
    float* __restrict__ outp)
{
    extern __shared__ __nv_bfloat16 sm[];

    const int tid  = threadIdx.x;
    const int wid  = tid >> 5;
    const int lane = tid & 31;
    const int gid  = lane >> 2;      // 0..7
    const int tig  = lane & 3;       // 0..3
    const int n0 = blockIdx.x * 128;
    const int m0 = blockIdx.y * 128;
    const int wm = (wid >> 2) * 32;  // warp m offset {0,32,64,96}
    const int wn = (wid & 3) * 32;   // warp n offset {0,32,64,96}

    const __nv_bfloat16* gsrc[4];
    gsrc[0] = (MODE == 0 ? g_xt_hi : g_yhi) + (size_t)m0 * SDIM;
    gsrc[1] = (MODE == 0 ? g_xt_lo : g_ylo) + (size_t)m0 * SDIM;
    gsrc[2] = (MODE == 0 ? g_Wp_hi : g_Wo_hi) + (size_t)n0 * SDIM;
    gsrc[3] = (MODE == 0 ? g_Wp_lo : g_Wo_lo) + (size_t)n0 * SDIM;

    const uint32_t sbase = smem_u32(sm);
    const int row0 = tid >> 2, seg = tid & 3;

    auto prefetch = [&](int stage, int k0g) {
        uint32_t sst = sbase + (uint32_t)stage * STAGE_E * 2;
#pragma unroll
        for (int t4 = 0; t4 < 4; ++t4) {
            uint32_t sa = sst + (uint32_t)(t4 * TILE_E + row0 * TSTR + seg * 8) * 2;
            cp16(sa, gsrc[t4] + (size_t)row0 * SDIM + k0g + seg * 8);
        }
        cp_commit();
    };

    float acc[2][4][4];
#pragma unroll
    for (int i = 0; i < 2; ++i)
#pragma unroll
        for (int j = 0; j < 4; ++j)
#pragma unroll
            for (int c = 0; c < 4; ++c) acc[i][j][c] = 0.f;

    prefetch(0, 0);
    prefetch(1, 32);

    const int a_row  = wm + (lane & 15);
    const int a_koff = (lane >> 4) * 8;
    const int b_row4  = wn + (lane & 7) + ((lane >> 4) << 3);
    const int b_koff4 = ((lane >> 3) & 1) * 8;

    const int KC = SDIM / 32;  // 12
    for (int kc = 0; kc < KC; ++kc) {
        const int cur = kc & 1;
        if (kc + 2 <= KC) cp_wait<1>(); else cp_wait<0>();
        __syncthreads();

        const uint32_t stile = sbase + (uint32_t)(cur * STAGE_E) * 2;
        const uint32_t sAhi = stile;
        const uint32_t sAlo = stile + TILE_E * 2;
        const uint32_t sBhi = stile + 2 * TILE_E * 2;
        const uint32_t sBlo = stile + 3 * TILE_E * 2;

#pragma unroll
        for (int ks = 0; ks < 2; ++ks) {
            const int kk = ks * 16;
            uint32_t ah[2][4], al[2][4], bh[2][4], bl[2][4];
#pragma unroll
            for (int mt = 0; mt < 2; ++mt) {
                uint32_t off = (uint32_t)((a_row + mt * 16) * TSTR + kk + a_koff) * 2;
                ldm_x4(ah[mt], sAhi + off);
                ldm_x4(al[mt], sAlo + off);
            }
#pragma unroll
            for (int p = 0; p < 2; ++p) {
                uint32_t off = (uint32_t)((b_row4 + p * 16) * TSTR + kk + b_koff4) * 2;
                ldm_x4(bh[p], sBhi + off);
                ldm_x4(bl[p], sBlo + off);
            }
#pragma unroll
            for (int mt = 0; mt < 2; ++mt)
#pragma unroll
                for (int nt = 0; nt < 4; ++nt) {
                    const uint32_t* bph = &bh[nt >> 1][(nt & 1) * 2];
                    const uint32_t* bpl = &bl[nt >> 1][(nt & 1) * 2];
                    mma16816(acc[mt][nt], ah[mt], bph);
                    mma16816(acc[mt][nt], ah[mt], bpl);
                    mma16816(acc[mt][nt], al[mt], bph);
                }
        }
        if (kc + 2 < KC) {
            __syncthreads();
            prefetch(cur, (kc + 2) * 32);
        }
    }

    // ---------------- epilogue ----------------
    if (MODE == 0) {
#pragma unroll
        for (int mt = 0; mt < 2; ++mt) {
#pragma unroll
            for (int nt = 0; nt < 4; ++nt) {
                const int m = m0 + wm + mt * 16 + gid;
                const int n = n0 + wn + nt * 8 + tig * 2;
#pragma unroll
                for (int half = 0; half < 2; ++half) {
                    const int mm = m + half * 8;
                    const float v0 = acc[mt][nt][half * 2 + 0];
                    const float v1 = acc[mt][nt][half * 2 + 1];
                    if (n < SDIM) {
                        g_xin[(size_t)mm * SDIM + n]     = v0 + bias[n];
                        g_xin[(size_t)mm * SDIM + n + 1] = v1 + bias[n + 1];
                    } else if (n < 2 * SDIM) {
                        const int nd = n - SDIM;
                        g_dsp[(size_t)mm * SDIM + nd]     = softplusf(v0 + bias[n] + dtb[nd]);
                        g_dsp[(size_t)mm * SDIM + nd + 1] = softplusf(v1 + bias[n + 1] + dtb[nd + 1]);
                    } else if (n < 2 * SDIM + DST) {
                        const int nd = n - 2 * SDIM;
                        g_Bm[(size_t)mm * DST + nd]     = v0 + bias[n];
                        g_Bm[(size_t)mm * DST + nd + 1] = v1 + bias[n + 1];
                    } else if (n < P_TOT) {
                        const int nd = n - (2 * SDIM + DST);
                        g_Cm[(size_t)mm * DST + nd]     = v0 + bias[n];
                        g_Cm[(size_t)mm * DST + nd + 1] = v1 + bias[n + 1];
                    }
                }
            }
        }
    } else {
        const int bq = m0 >> 12;
        const int l0 = m0 & 4095;
#pragma unroll
        for (int mt = 0; mt < 2; ++mt) {
#pragma unroll
            for (int nt = 0; nt < 4; ++nt) {
                const int l = l0 + wm + mt * 16 + gid;
                const int n = n0 + wn + nt * 8 + tig * 2;
                const float b0 = bias[n], b1 = bias[n + 1];
                float* r0 = &outp[((size_t)(bq * SDIM + n)) * L_SEQ + l];
                float* r1 = &outp[((size_t)(bq * SDIM + n + 1)) * L_SEQ + l];
                r0[0] = acc[mt][nt][0] + b0;
                r1[0] = acc[mt][nt][1] + b1;
                r0[8] = acc[mt][nt][2] + b0;
                r1[8] = acc[mt][nt][3] + b1;
            }
        }
    }
}

// ============================ scan kernels (8 states/lane, 2 lanes/channel) ============================
// 256 threads = 128 channels/block; tid&1 selects state half (n = half*8 .. half*8+7)
__global__ __launch_bounds__(256) void scanA_kernel(const float* __restrict__ Alog)
{
    __shared__ float Bsh[T_CHK * DST];   // 2KB

    const int tid  = threadIdx.x;
    const int chl  = tid >> 1;           // 0..127
    const int half = tid & 1;
    const int d    = blockIdx.x * 128 + chl;
    const int b    = blockIdx.y;
    const int chk  = blockIdx.z;
    const int t0   = chk * T_CHK;
    const int ch   = b * SDIM + d;
    const int n0s  = half * 8;

    if (tid < 128) {  // stage B chunk: 512 floats = 128 float4
        const float4* src = reinterpret_cast<const float4*>(&g_Bm[((size_t)(b * L_SEQ + t0)) * DST]);
        reinterpret_cast<float4*>(Bsh)[tid] = __ldg(&src[tid]);
    }

    float A[8], h[8], aP[8];
#pragma unroll
    for (int j = 0; j < 8; ++j) {
        A[j] = -expf(__ldg(&Alog[d * DST + n0s + j]));
        h[j] = 0.f; aP[j] = 1.f;
    }
    __syncthreads();

    size_t ix = ((size_t)(b * L_SEQ + t0)) * SDIM + d;
#pragma unroll 4
    for (int t = 0; t < T_CHK; ++t) {
        float dt = __ldg(&g_dsp[ix]);
        float xv = __ldg(&g_xin[ix]);
        float u  = dt * xv;
        const float4* Bq = reinterpret_cast<const float4*>(&Bsh[t * DST + n0s]);
        float4 b0 = Bq[0], b1 = Bq[1];
        const float bb[8] = {b0.x, b0.y, b0.z, b0.w, b1.x, b1.y, b1.z, b1.w};
#pragma unroll
        for (int j = 0; j < 8; ++j) {
            float e = __expf(dt * A[j]);
            h[j] = fmaf(e, h[j], u * bb[j]);
            aP[j] *= e;
        }
        ix += SDIM;
    }

    const size_t ob = (size_t)chk * CSTATES + (size_t)ch * DST + n0s;
    *reinterpret_cast<float4*>(&g_aP[ob])     = make_float4(aP[0], aP[1], aP[2], aP[3]);
    *reinterpret_cast<float4*>(&g_aP[ob + 4]) = make_float4(aP[4], aP[5], aP[6], aP[7]);
    *reinterpret_cast<float4*>(&g_hP[ob])     = make_float4(h[0], h[1], h[2], h[3]);
    *reinterpret_cast<float4*>(&g_hP[ob + 4]) = make_float4(h[4], h[5], h[6], h[7]);
}

__global__ __launch_bounds__(256) void scanB_kernel()
{
    const int tid = blockIdx.x * 256 + threadIdx.x;
    float h = 0.f;
#pragma unroll 8
    for (int c = 0; c < N_CHK; ++c) {
        g_h0[c * CSTATES + tid] = h;
        h = fmaf(__ldg(&g_aP[c * CSTATES + tid]), h, __ldg(&g_hP[c * CSTATES + tid]));
    }
}

__global__ __launch_bounds__(256) void scanC_kernel(
    const float* __restrict__ Alog, const float* __restrict__ Dp)
{
    __shared__ float Bsh[T_CHK * DST];
    __shared__ float Csh[T_CHK * DST];

    const int tid  = threadIdx.x;
    const int chl  = tid >> 1;
    const int half = tid & 1;
    const int d    = blockIdx.x * 128 + chl;
    const int b    = blockIdx.y;
    const int chk  = blockIdx.z;
    const int t0   = chk * T_CHK;
    const int ch   = b * SDIM + d;
    const int n0s  = half * 8;

    {   // stage B (threads 0..127) and C (threads 128..255)
        const float4* srcB = reinterpret_cast<const float4*>(&g_Bm[((size_t)(b * L_SEQ + t0)) * DST]);
        const float4* srcC = reinterpret_cast<const float4*>(&g_Cm[((size_t)(b * L_SEQ + t0)) * DST]);
        if (tid < 128) reinterpret_cast<float4*>(Bsh)[tid]       = __ldg(&srcB[tid]);
        else           reinterpret_cast<float4*>(Csh)[tid - 128] = __ldg(&srcC[tid - 128]);
    }

    float A[8], h[8];
#pragma unroll
    for (int j = 0; j < 8; ++j)
        A[j] = -expf(__ldg(&Alog[d * DST + n0s + j]));
    {
        const size_t hb = (size_t)chk * CSTATES + (size_t)ch * DST + n0s;
        float4 v0 = *reinterpret_cast<const float4*>(&g_h0[hb]);
        float4 v1 = *reinterpret_cast<const float4*>(&g_h0[hb + 4]);
        h[0]=v0.x; h[1]=v0.y; h[2]=v0.z; h[3]=v0.w;
        h[4]=v1.x; h[5]=v1.y; h[6]=v1.z; h[7]=v1.w;
    }
    const float Dd = __ldg(&Dp[d]);
    __syncthreads();

    size_t ix = ((size_t)(b * L_SEQ + t0)) * SDIM + d;
#pragma unroll 4
    for (int t = 0; t < T_CHK; ++t) {
        float dt = __ldg(&g_dsp[ix]);
        float xv = __ldg(&g_xin[ix]);
        float u  = dt * xv;
        const float4* Bq = reinterpret_cast<const float4*>(&Bsh[t * DST + n0s]);
        const float4* Cq = reinterpret_cast<const float4*>(&Csh[t * DST + n0s]);
        float4 b0 = Bq[0], b1 = Bq[1];
        float4 c0 = Cq[0], c1 = Cq[1];
        const float bb[8] = {b0.x, b0.y, b0.z, b0.w, b1.x, b1.y, b1.z, b1.w};
        const float cc[8] = {c0.x, c0.y, c0.z, c0.w, c1.x, c1.y, c1.z, c1.w};
        float p = (half == 0) ? xv * Dd : 0.f;
#pragma unroll
        for (int j = 0; j < 8; ++j) {
            float e = __expf(dt * A[j]);
            h[j] = fmaf(e, h[j], u * bb[j]);
            p = fmaf(h[j], cc[j], p);
        }
        p += __shfl_xor_sync(0xffffffffu, p, 1);
        if (half == 0) {
            __nv_bfloat16 hi = __float2bfloat16(p);
            g_yhi[ix] = hi;
            g_ylo[ix] = __float2bfloat16(p - __bfloat162float(hi));
        }
        ix += SDIM;
    }
}

// ============================ launch ============================
extern "C" void kernel_launch(void* const* d_in, const int* in_sizes, int n_in,
                              void* d_out, int out_size)
{
    const float* x    = (const float*)d_in[0];
    const float* Wp   = (const float*)d_in[1];
    const float* bp   = (const float*)d_in[2];
    const float* Alog = (const float*)d_in[3];
    const float* D    = (const float*)d_in[4];
    const float* dtb  = (const float*)d_in[5];
    const float* Wo   = (const float*)d_in[6];
    const float* bo   = (const float*)d_in[7];
    float* out = (float*)d_out;

    static bool attr_done = false;
    if (!attr_done) {
        cudaFuncSetAttribute(gemm_mma<0>, cudaFuncAttributeMaxDynamicSharedMemorySize, GEMM_SMEM);
        cudaFuncSetAttribute(gemm_mma<1>, cudaFuncAttributeMaxDynamicSharedMemorySize, GEMM_SMEM);
        attr_done = true;
    }

    // prep: transpose x to [m][k] split-bf16; split weights into device globals
    transpose_split_kernel<<<dim3(L_SEQ / 32, SDIM / 32, BATCH), dim3(32, 8)>>>(x);
    convWp_kernel<<<(NP_PAD * SDIM + 255) / 256, 256>>>(Wp);
    convWo_kernel<<<(SDIM * SDIM + 255) / 256, 256>>>(Wo);

    // proj GEMM (HMMA) with fused region split + softplus
    gemm_mma<0><<<dim3(NP_PAD / 128, M_TOT / 128), 512, GEMM_SMEM>>>(bp, dtb, nullptr);

    // selective scan (chunked, 8 states/lane)
    dim3 gs(SDIM / 128, BATCH, N_CHK);           // (3, 4, 128)
    scanA_kernel<<<gs, 256>>>(Alog);
    scanB_kernel<<<CSTATES / 256, 256>>>();
    scanC_kernel<<<gs, 256>>>(Alog, D);

    // out GEMM (HMMA) with direct fragment stores
    gemm_mma<1><<<dim3(SDIM / 128, M_TOT / 128), 512, GEMM_SMEM>>>(bo, nullptr, out);
}

// round 17
// speedup vs baseline: 1.0309x; 1.0009x over previous
#include <cuda_runtime.h>
#include <cuda_bf16.h>
#include <cstdint>
#include <cstddef>

#define L_SEQ 4096
#define SDIM  384
#define DST   16
#define BATCH 4
#define M_TOT (BATCH * L_SEQ)      // 16384
#define P_TOT (2 * SDIM + 2 * DST) // 800
#define NP_PAD 896                 // 7*128 padded proj output dim
#define NCH   (BATCH * SDIM)
#define T_CHK 32
#define N_CHK (L_SEQ / T_CHK)      // 128
#define CSTATES (NCH * DST)        // 24576

// ---------------- scratch (referenced ONLY inside device code) ----------------
__device__ __align__(16) float g_xin[M_TOT * SDIM];
__device__ __align__(16) float g_dsp[M_TOT * SDIM];
__device__ __align__(16) float g_Bm [M_TOT * DST];
__device__ __align__(16) float g_Cm [M_TOT * DST];
__device__ __align__(16) float g_aP [N_CHK * CSTATES];
__device__ __align__(16) float g_hP [N_CHK * CSTATES];
__device__ __align__(16) float g_h0 [N_CHK * CSTATES];

__device__ __align__(16) __nv_bfloat16 g_xt_hi[(size_t)M_TOT * SDIM];
__device__ __align__(16) __nv_bfloat16 g_xt_lo[(size_t)M_TOT * SDIM];
__device__ __align__(16) __nv_bfloat16 g_yhi [(size_t)M_TOT * SDIM];
__device__ __align__(16) __nv_bfloat16 g_ylo [(size_t)M_TOT * SDIM];
__device__ __align__(16) __nv_bfloat16 g_Wp_hi[NP_PAD * SDIM];
__device__ __align__(16) __nv_bfloat16 g_Wp_lo[NP_PAD * SDIM];
__device__ __align__(16) __nv_bfloat16 g_Wo_hi[SDIM * SDIM];
__device__ __align__(16) __nv_bfloat16 g_Wo_lo[SDIM * SDIM];

__device__ __forceinline__ float softplusf(float z) {
    if (z > 20.f) return z;
    return log1pf(__expf(z));
}

__device__ __forceinline__ uint32_t smem_u32(const void* p) {
    uint32_t a;
    asm("{ .reg .u64 t; cvta.to.shared.u64 t, %1; cvt.u32.u64 %0, t; }" : "=r"(a) : "l"(p));
    return a;
}

__device__ __forceinline__ void cp16(uint32_t saddr, const void* gptr) {
    asm volatile("cp.async.cg.shared.global [%0], [%1], 16;" :: "r"(saddr), "l"(gptr));
}
__device__ __forceinline__ void cp_commit() {
    asm volatile("cp.async.commit_group;" ::: "memory");
}
template<int N>
__device__ __forceinline__ void cp_wait() {
    asm volatile("cp.async.wait_group %0;" :: "n"(N) : "memory");
}

__device__ __forceinline__ void ldm_x4(uint32_t* r, uint32_t addr) {
    asm volatile("ldmatrix.sync.aligned.m8n8.x4.shared.b16 {%0,%1,%2,%3}, [%4];"
                 : "=r"(r[0]), "=r"(r[1]), "=r"(r[2]), "=r"(r[3]) : "r"(addr));
}
__device__ __forceinline__ void mma16816(float* c, const uint32_t* a, const uint32_t* b) {
    asm volatile(
        "mma.sync.aligned.m16n8k16.row.col.f32.bf16.bf16.f32 "
        "{%0,%1,%2,%3}, {%4,%5,%6,%7}, {%8,%9}, {%0,%1,%2,%3};"
        : "+f"(c[0]), "+f"(c[1]), "+f"(c[2]), "+f"(c[3])
        : "r"(a[0]), "r"(a[1]), "r"(a[2]), "r"(a[3]), "r"(b[0]), "r"(b[1]));
}

// ============================ prep kernels ============================
__global__ __launch_bounds__(256) void transpose_split_kernel(const float* __restrict__ x)
{
    __shared__ float T[32][33];
    const int tx = threadIdx.x, ty = threadIdx.y;
    const int l0 = blockIdx.x * 32, c0 = blockIdx.y * 32, b = blockIdx.z;
#pragma unroll
    for (int i = 0; i < 4; ++i) {
        int c = c0 + ty + i * 8;
        T[ty + i * 8][tx] = x[((size_t)b * SDIM + c) * L_SEQ + l0 + tx];
    }
    __syncthreads();
#pragma unroll
    for (int i = 0; i < 4; ++i) {
        int l = l0 + ty + i * 8;
        size_t m = (size_t)b * L_SEQ + l;
        float v = T[tx][ty + i * 8];
        __nv_bfloat16 hi = __float2bfloat16(v);
        float lo = v - __bfloat162float(hi);
        g_xt_hi[m * SDIM + c0 + tx] = hi;
        g_xt_lo[m * SDIM + c0 + tx] = __float2bfloat16(lo);
    }
}

__global__ __launch_bounds__(256) void convWp_kernel(const float* __restrict__ W)
{
    int idx = blockIdx.x * 256 + threadIdx.x;
    if (idx >= NP_PAD * SDIM) return;
    int n = idx / SDIM;
    float v = (n < P_TOT) ? W[idx] : 0.f;
    __nv_bfloat16 h = __float2bfloat16(v);
    g_Wp_hi[idx] = h;
    g_Wp_lo[idx] = __float2bfloat16(v - __bfloat162float(h));
}

__global__ __launch_bounds__(256) void convWo_kernel(const float* __restrict__ W)
{
    int idx = blockIdx.x * 256 + threadIdx.x;
    if (idx >= SDIM * SDIM) return;
    float v = W[idx];
    __nv_bfloat16 h = __float2bfloat16(v);
    g_Wo_hi[idx] = h;
    g_Wo_lo[idx] = __float2bfloat16(v - __bfloat162float(h));
}

// ============================ HMMA GEMM (padding-aware warp skip) ============================
// D[128m x 128n] = (Ahi+Alo)[m][384] . (Bhi+Blo)[n][384]^T  (3-term split)
// 512 threads = 16 warps as 4(m) x 4(n); warp tile 32x32; BK=32; 2-stage cp.async.
// MODE 0: warps entirely in the zero-padded N region (n0+wn >= P_TOT) skip all
// fragment loads + MMAs (warp-uniform predicate) — deflates the 75%-padded tile 6.
#define TSTR 40                         // smem stride (bf16 elements); row = 80B
#define TILE_E (128 * TSTR)             // bf16 elements per tile
#define STAGE_E (4 * TILE_E)            // 4 tiles per stage
#define GEMM_SMEM (2 * STAGE_E * 2)     // 81920 bytes

template<int MODE>
__global__ __launch_bounds__(512, 2) void gemm_mma(
    const float* __restrict__ bias, const float* __restrict__ dtb,
    float* __restrict__ outp)
{
    extern __shared__ __nv_bfloat16 sm[];

    const int tid  = threadIdx.x;
    const int wid  = tid >> 5;
    const int lane = tid & 31;
    const int gid  = lane >> 2;      // 0..7
    const int tig  = lane & 3;       // 0..3
    const int n0 = blockIdx.x * 128;
    const int m0 = blockIdx.y * 128;
    const int wm = (wid >> 2) * 32;  // warp m offset {0,32,64,96}
    const int wn = (wid & 3) * 32;   // warp n offset {0,32,64,96}

    // warp-uniform: does this warp produce any valid output columns?
    const bool nact = (MODE != 0) || (n0 + wn < P_TOT);

    const __nv_bfloat16* gsrc[4];
    gsrc[0] = (MODE == 0 ? g_xt_hi : g_yhi) + (size_t)m0 * SDIM;
    gsrc[1] = (MODE == 0 ? g_xt_lo : g_ylo) + (size_t)m0 * SDIM;
    gsrc[2] = (MODE == 0 ? g_Wp_hi : g_Wo_hi) + (size_t)n0 * SDIM;
    gsrc[3] = (MODE == 0 ? g_Wp_lo : g_Wo_lo) + (size_t)n0 * SDIM;

    const uint32_t sbase = smem_u32(sm);
    const int row0 = tid >> 2, seg = tid & 3;

    auto prefetch = [&](int stage, int k0g) {
        uint32_t sst = sbase + (uint32_t)stage * STAGE_E * 2;
#pragma unroll
        for (int t4 = 0; t4 < 4; ++t4) {
            uint32_t sa = sst + (uint32_t)(t4 * TILE_E + row0 * TSTR + seg * 8) * 2;
            cp16(sa, gsrc[t4] + (size_t)row0 * SDIM + k0g + seg * 8);
        }
        cp_commit();
    };

    float acc[2][4][4];
#pragma unroll
    for (int i = 0; i < 2; ++i)
#pragma unroll
        for (int j = 0; j < 4; ++j)
#pragma unroll
            for (int c = 0; c < 4; ++c) acc[i][j][c] = 0.f;

    prefetch(0, 0);
    prefetch(1, 32);

    const int a_row  = wm + (lane & 15);
    const int a_koff = (lane >> 4) * 8;
    const int b_row4  = wn + (lane & 7) + ((lane >> 4) << 3);
    const int b_koff4 = ((lane >> 3) & 1) * 8;

    const int KC = SDIM / 32;  // 12
    for (int kc = 0; kc < KC; ++kc) {
        const int cur = kc & 1;
        if (kc + 2 <= KC) cp_wait<1>(); else cp_wait<0>();
        __syncthreads();

        const uint32_t stile = sbase + (uint32_t)(cur * STAGE_E) * 2;
        const uint32_t sAhi = stile;
        const uint32_t sAlo = stile + TILE_E * 2;
        const uint32_t sBhi = stile + 2 * TILE_E * 2;
        const uint32_t sBlo = stile + 3 * TILE_E * 2;

        if (nact) {
#pragma unroll
            for (int ks = 0; ks < 2; ++ks) {
                const int kk = ks * 16;
                uint32_t ah[2][4], al[2][4], bh[2][4], bl[2][4];
#pragma unroll
                for (int mt = 0; mt < 2; ++mt) {
                    uint32_t off = (uint32_t)((a_row + mt * 16) * TSTR + kk + a_koff) * 2;
                    ldm_x4(ah[mt], sAhi + off);
                    ldm_x4(al[mt], sAlo + off);
                }
#pragma unroll
                for (int p = 0; p < 2; ++p) {
                    uint32_t off = (uint32_t)((b_row4 + p * 16) * TSTR + kk + b_koff4) * 2;
                    ldm_x4(bh[p], sBhi + off);
                    ldm_x4(bl[p], sBlo + off);
                }
#pragma unroll
                for (int mt = 0; mt < 2; ++mt)
#pragma unroll
                    for (int nt = 0; nt < 4; ++nt) {
                        const uint32_t* bph = &bh[nt >> 1][(nt & 1) * 2];
                        const uint32_t* bpl = &bl[nt >> 1][(nt & 1) * 2];
                        mma16816(acc[mt][nt], ah[mt], bph);
                        mma16816(acc[mt][nt], ah[mt], bpl);
                        mma16816(acc[mt][nt], al[mt], bph);
                    }
            }
        }
        if (kc + 2 < KC) {
            __syncthreads();
            prefetch(cur, (kc + 2) * 32);
        }
    }

    // ---------------- epilogue ----------------
    if (MODE == 0) {
        if (!nact) return;
#pragma unroll
        for (int mt = 0; mt < 2; ++mt) {
#pragma unroll
            for (int nt = 0; nt < 4; ++nt) {
                const int m = m0 + wm + mt * 16 + gid;
                const int n = n0 + wn + nt * 8 + tig * 2;
#pragma unroll
                for (int half = 0; half < 2; ++half) {
                    const int mm = m + half * 8;
                    const float v0 = acc[mt][nt][half * 2 + 0];
                    const float v1 = acc[mt][nt][half * 2 + 1];
                    if (n < SDIM) {
                        g_xin[(size_t)mm * SDIM + n]     = v0 + bias[n];
                        g_xin[(size_t)mm * SDIM + n + 1] = v1 + bias[n + 1];
                    } else if (n < 2 * SDIM) {
                        const int nd = n - SDIM;
                        g_dsp[(size_t)mm * SDIM + nd]     = softplusf(v0 + bias[n] + dtb[nd]);
                        g_dsp[(size_t)mm * SDIM + nd + 1] = softplusf(v1 + bias[n + 1] + dtb[nd + 1]);
                    } else if (n < 2 * SDIM + DST) {
                        const int nd = n - 2 * SDIM;
                        g_Bm[(size_t)mm * DST + nd]     = v0 + bias[n];
                        g_Bm[(size_t)mm * DST + nd + 1] = v1 + bias[n + 1];
                    } else if (n < P_TOT) {
                        const int nd = n - (2 * SDIM + DST);
                        g_Cm[(size_t)mm * DST + nd]     = v0 + bias[n];
                        g_Cm[(size_t)mm * DST + nd + 1] = v1 + bias[n + 1];
                    }
                }
            }
        }
    } else {
        const int bq = m0 >> 12;
        const int l0 = m0 & 4095;
#pragma unroll
        for (int mt = 0; mt < 2; ++mt) {
#pragma unroll
            for (int nt = 0; nt < 4; ++nt) {
                const int l = l0 + wm + mt * 16 + gid;
                const int n = n0 + wn + nt * 8 + tig * 2;
                const float b0 = bias[n], b1 = bias[n + 1];
                float* r0 = &outp[((size_t)(bq * SDIM + n)) * L_SEQ + l];
                float* r1 = &outp[((size_t)(bq * SDIM + n + 1)) * L_SEQ + l];
                r0[0] = acc[mt][nt][0] + b0;
                r1[0] = acc[mt][nt][1] + b1;
                r0[8] = acc[mt][nt][2] + b0;
                r1[8] = acc[mt][nt][3] + b1;
            }
        }
    }
}

// ============================ scan kernels (8 states/lane, 2 lanes/channel) ============================
__global__ __launch_bounds__(256) void scanA_kernel(const float* __restrict__ Alog)
{
    __shared__ float Bsh[T_CHK * DST];

    const int tid  = threadIdx.x;
    const int chl  = tid >> 1;
    const int half = tid & 1;
    const int d    = blockIdx.x * 128 + chl;
    const int b    = blockIdx.y;
    const int chk  = blockIdx.z;
    const int t0   = chk * T_CHK;
    const int ch   = b * SDIM + d;
    const int n0s  = half * 8;

    if (tid < 128) {
        const float4* src = reinterpret_cast<const float4*>(&g_Bm[((size_t)(b * L_SEQ + t0)) * DST]);
        reinterpret_cast<float4*>(Bsh)[tid] = __ldg(&src[tid]);
    }

    float A[8], h[8], aP[8];
#pragma unroll
    for (int j = 0; j < 8; ++j) {
        A[j] = -expf(__ldg(&Alog[d * DST + n0s + j]));
        h[j] = 0.f; aP[j] = 1.f;
    }
    __syncthreads();

    size_t ix = ((size_t)(b * L_SEQ + t0)) * SDIM + d;
#pragma unroll 4
    for (int t = 0; t < T_CHK; ++t) {
        float dt = __ldg(&g_dsp[ix]);
        float xv = __ldg(&g_xin[ix]);
        float u  = dt * xv;
        const float4* Bq = reinterpret_cast<const float4*>(&Bsh[t * DST + n0s]);
        float4 b0 = Bq[0], b1 = Bq[1];
        const float bb[8] = {b0.x, b0.y, b0.z, b0.w, b1.x, b1.y, b1.z, b1.w};
#pragma unroll
        for (int j = 0; j < 8; ++j) {
            float e = __expf(dt * A[j]);
            h[j] = fmaf(e, h[j], u * bb[j]);
            aP[j] *= e;
        }
        ix += SDIM;
    }

    const size_t ob = (size_t)chk * CSTATES + (size_t)ch * DST + n0s;
    *reinterpret_cast<float4*>(&g_aP[ob])     = make_float4(aP[0], aP[1], aP[2], aP[3]);
    *reinterpret_cast<float4*>(&g_aP[ob + 4]) = make_float4(aP[4], aP[5], aP[6], aP[7]);
    *reinterpret_cast<float4*>(&g_hP[ob])     = make_float4(h[0], h[1], h[2], h[3]);
    *reinterpret_cast<float4*>(&g_hP[ob + 4]) = make_float4(h[4], h[5], h[6], h[7]);
}

__global__ __launch_bounds__(256) void scanB_kernel()
{
    const int tid = blockIdx.x * 256 + threadIdx.x;
    float h = 0.f;
#pragma unroll 8
    for (int c = 0; c < N_CHK; ++c) {
        g_h0[c * CSTATES + tid] = h;
        h = fmaf(__ldg(&g_aP[c * CSTATES + tid]), h, __ldg(&g_hP[c * CSTATES + tid]));
    }
}

__global__ __launch_bounds__(256) void scanC_kernel(
    const float* __restrict__ Alog, const float* __restrict__ Dp)
{
    __shared__ float Bsh[T_CHK * DST];
    __shared__ float Csh[T_CHK * DST];

    const int tid  = threadIdx.x;
    const int chl  = tid >> 1;
    const int half = tid & 1;
    const int d    = blockIdx.x * 128 + chl;
    const int b    = blockIdx.y;
    const int chk  = blockIdx.z;
    const int t0   = chk * T_CHK;
    const int ch   = b * SDIM + d;
    const int n0s  = half * 8;

    {
        const float4* srcB = reinterpret_cast<const float4*>(&g_Bm[((size_t)(b * L_SEQ + t0)) * DST]);
        const float4* srcC = reinterpret_cast<const float4*>(&g_Cm[((size_t)(b * L_SEQ + t0)) * DST]);
        if (tid < 128) reinterpret_cast<float4*>(Bsh)[tid]       = __ldg(&srcB[tid]);
        else           reinterpret_cast<float4*>(Csh)[tid - 128] = __ldg(&srcC[tid - 128]);
    }

    float A[8], h[8];
#pragma unroll
    for (int j = 0; j < 8; ++j)
        A[j] = -expf(__ldg(&Alog[d * DST + n0s + j]));
    {
        const size_t hb = (size_t)chk * CSTATES + (size_t)ch * DST + n0s;
        float4 v0 = *reinterpret_cast<const float4*>(&g_h0[hb]);
        float4 v1 = *reinterpret_cast<const float4*>(&g_h0[hb + 4]);
        h[0]=v0.x; h[1]=v0.y; h[2]=v0.z; h[3]=v0.w;
        h[4]=v1.x; h[5]=v1.y; h[6]=v1.z; h[7]=v1.w;
    }
    const float Dd = __ldg(&Dp[d]);
    __syncthreads();

    size_t ix = ((size_t)(b * L_SEQ + t0)) * SDIM + d;
#pragma unroll 4
    for (int t = 0; t < T_CHK; ++t) {
        float dt = __ldg(&g_dsp[ix]);
        float xv = __ldg(&g_xin[ix]);
        float u  = dt * xv;
        const float4* Bq = reinterpret_cast<const float4*>(&Bsh[t * DST + n0s]);
        const float4* Cq = reinterpret_cast<const float4*>(&Csh[t * DST + n0s]);
        float4 b0 = Bq[0], b1 = Bq[1];
        float4 c0 = Cq[0], c1 = Cq[1];
        const float bb[8] = {b0.x, b0.y, b0.z, b0.w, b1.x, b1.y, b1.z, b1.w};
        const float cc[8] = {c0.x, c0.y, c0.z, c0.w, c1.x, c1.y, c1.z, c1.w};
        float p = (half == 0) ? xv * Dd : 0.f;
#pragma unroll
        for (int j = 0; j < 8; ++j) {
            float e = __expf(dt * A[j]);
            h[j] = fmaf(e, h[j], u * bb[j]);
            p = fmaf(h[j], cc[j], p);
        }
        p += __shfl_xor_sync(0xffffffffu, p, 1);
        if (half == 0) {
            __nv_bfloat16 hi = __float2bfloat16(p);
            g_yhi[ix] = hi;
            g_ylo[ix] = __float2bfloat16(p - __bfloat162float(hi));
        }
        ix += SDIM;
    }
}

// ============================ launch ============================
extern "C" void kernel_launch(void* const* d_in, const int* in_sizes, int n_in,
                              void* d_out, int out_size)
{
    const float* x    = (const float*)d_in[0];
    const float* Wp   = (const float*)d_in[1];
    const float* bp   = (const float*)d_in[2];
    const float* Alog = (const float*)d_in[3];
    const float* D    = (const float*)d_in[4];
    const float* dtb  = (const float*)d_in[5];
    const float* Wo   = (const float*)d_in[6];
    const float* bo   = (const float*)d_in[7];
    float* out = (float*)d_out;

    static bool attr_done = false;
    if (!attr_done) {
        cudaFuncSetAttribute(gemm_mma<0>, cudaFuncAttributeMaxDynamicSharedMemorySize, GEMM_SMEM);
        cudaFuncSetAttribute(gemm_mma<1>, cudaFuncAttributeMaxDynamicSharedMemorySize, GEMM_SMEM);
        attr_done = true;
    }

    // prep: transpose x to [m][k] split-bf16; split weights into device globals
    transpose_split_kernel<<<dim3(L_SEQ / 32, SDIM / 32, BATCH), dim3(32, 8)>>>(x);
    convWp_kernel<<<(NP_PAD * SDIM + 255) / 256, 256>>>(Wp);
    convWo_kernel<<<(SDIM * SDIM + 255) / 256, 256>>>(Wo);

    // proj GEMM (HMMA, padding-aware) with fused region split + softplus
    gemm_mma<0><<<dim3(NP_PAD / 128, M_TOT / 128), 512, GEMM_SMEM>>>(bp, dtb, nullptr);

    // selective scan (chunked, 8 states/lane)
    dim3 gs(SDIM / 128, BATCH, N_CHK);           // (3, 4, 128)
    scanA_kernel<<<gs, 256>>>(Alog);
    scanB_kernel<<<CSTATES / 256, 256>>>();
    scanC_kernel<<<gs, 256>>>(Alog, D);

    // out GEMM (HMMA) with direct fragment stores
    gemm_mma<1><<<dim3(SDIM / 128, M_TOT / 128), 512, GEMM_SMEM>>>(bo, nullptr, out);
}